// round 4
// baseline (speedup 1.0000x reference)
#include <cuda_runtime.h>
#include <cuda_bf16.h>
#include <math.h>
#include <stdint.h>

#define HIDDEN   2048
#define NHEADS   16
#define HDIM     128
#define BATCH    2
#define SEQ      2048
#define BH       (BATCH * NHEADS)
#define MROWS    (BATCH * SEQ)
#define INV_NORM 0.08838834764831845f   // 1/sqrt(128)

#define KB        32
#define STAGE_B   32768
#define NSTAGE    3
#define EPI_STR   132
#define SMEM_DYN  (NSTAGE * STAGE_B)

// ===================== scratch (static __device__, no allocation) ============
__device__ __align__(128) __nv_bfloat16 g_xh[(size_t)MROWS * HIDDEN];
__device__ __align__(128) __nv_bfloat16 g_xl[(size_t)MROWS * HIDDEN];
__device__ __align__(128) __nv_bfloat16 g_wqh[(size_t)HIDDEN * HIDDEN];
__device__ __align__(128) __nv_bfloat16 g_wql[(size_t)HIDDEN * HIDDEN];
__device__ __align__(128) __nv_bfloat16 g_wkh[(size_t)HIDDEN * HIDDEN];
__device__ __align__(128) __nv_bfloat16 g_wkl[(size_t)HIDDEN * HIDDEN];
__device__ __align__(128) __nv_bfloat16 g_wvh[(size_t)HIDDEN * HIDDEN];
__device__ __align__(128) __nv_bfloat16 g_wvl[(size_t)HIDDEN * HIDDEN];
__device__ __align__(128) __nv_bfloat16 g_wdh[(size_t)HIDDEN * HIDDEN];
__device__ __align__(128) __nv_bfloat16 g_wdl[(size_t)HIDDEN * HIDDEN];

__device__ __align__(128) __nv_bfloat16 g_qh[(size_t)BH * SEQ * HDIM];
__device__ __align__(128) __nv_bfloat16 g_ql[(size_t)BH * SEQ * HDIM];
__device__ __align__(128) __nv_bfloat16 g_kh[(size_t)BH * SEQ * HDIM];
__device__ __align__(128) __nv_bfloat16 g_kl[(size_t)BH * SEQ * HDIM];
__device__ __align__(128) __nv_bfloat16 g_vTh[(size_t)BH * HDIM * SEQ];
__device__ __align__(128) __nv_bfloat16 g_vTl[(size_t)BH * HDIM * SEQ];
__device__ __align__(128) __nv_bfloat16 g_ch[(size_t)MROWS * HIDDEN];
__device__ __align__(128) __nv_bfloat16 g_cl[(size_t)MROWS * HIDDEN];

// ===================== helpers ===============================================
static __device__ __forceinline__ uint32_t s2u(const void* p) {
    uint32_t a;
    asm("{ .reg .u64 t; cvta.to.shared.u64 t, %1; cvt.u32.u64 %0, t; }"
        : "=r"(a) : "l"(p));
    return a;
}
static __device__ __forceinline__ void ldm4(uint32_t (&r)[4], uint32_t addr) {
    asm volatile("ldmatrix.sync.aligned.m8n8.x4.shared.b16 {%0,%1,%2,%3}, [%4];"
                 : "=r"(r[0]), "=r"(r[1]), "=r"(r[2]), "=r"(r[3]) : "r"(addr));
}
static __device__ __forceinline__ void mma16816(float (&c)[4],
                                                const uint32_t (&a)[4],
                                                const uint32_t* b) {
    asm volatile("mma.sync.aligned.m16n8k16.row.col.f32.bf16.bf16.f32 "
                 "{%0,%1,%2,%3}, {%4,%5,%6,%7}, {%8,%9}, {%0,%1,%2,%3};"
                 : "+f"(c[0]), "+f"(c[1]), "+f"(c[2]), "+f"(c[3])
                 : "r"(a[0]), "r"(a[1]), "r"(a[2]), "r"(a[3]),
                   "r"(b[0]), "r"(b[1]));
}
static __device__ __forceinline__ void split_bf(float x, __nv_bfloat16& h,
                                                __nv_bfloat16& l) {
    h = __float2bfloat16(x);
    l = __float2bfloat16(x - __bfloat162float(h));
}
static __device__ __forceinline__ void cpa16(uint32_t so, const void* g) {
    asm volatile("cp.async.cg.shared.global [%0], [%1], 16;" :: "r"(so), "l"(g));
}
// swizzles: tile rows of 64B / 128B / 256B
static __device__ __forceinline__ uint32_t swz(int row, int c16) {       // 64B rows
    return (uint32_t)(row * 64 + ((c16 ^ ((row >> 1) & 3)) << 4));
}
static __device__ __forceinline__ uint32_t swz128(int row, int c16) {    // 128B rows
    return (uint32_t)(row * 128 + ((c16 ^ (row & 7)) << 4));
}
static __device__ __forceinline__ uint32_t swz256(int row, int c16) {    // 256B rows
    return (uint32_t)(row * 256 + ((c16 ^ ((row & 7) << 1)) << 4));
}

// ===================== bf16x3 mma.sync GEMM core (projections) ===============
static __device__ __forceinline__ void mma_gemm(
    const __nv_bfloat16* __restrict__ Ah, const __nv_bfloat16* __restrict__ Al,
    const __nv_bfloat16* __restrict__ Bh, const __nv_bfloat16* __restrict__ Bl,
    int K, int lda, int ldb, float (&acc)[4][4][4]) {
    extern __shared__ char smem[];
    const uint32_t sb = s2u(smem);
    const int tid  = threadIdx.x;
    const int lane = tid & 31;
    const int wid  = tid >> 5;
    const int wm   = wid & 1;
    const int wn   = wid >> 1;
    const int NC   = K >> 5;

    const __nv_bfloat16* srcs[4] = { Ah, Al, Bh, Bl };
    const int lds[4] = { lda, lda, ldb, ldb };
    const int lrow = tid >> 2;
    const int lc16 = tid & 3;

#define ISSUE(cc)                                                              \
    {                                                                          \
        const int _c = (cc);                                                   \
        const uint32_t sbase = sb + (_c % NSTAGE) * STAGE_B;                   \
        _Pragma("unroll")                                                      \
        for (int mat = 0; mat < 4; mat++) {                                    \
            _Pragma("unroll")                                                  \
            for (int rep = 0; rep < 2; rep++) {                                \
                const int row = lrow + rep * 64;                               \
                const char* g = (const char*)(srcs[mat] +                      \
                                  (size_t)row * lds[mat] + _c * KB) + lc16*16; \
                const uint32_t so = sbase + mat * 8192 + swz(row, lc16);       \
                cpa16(so, g);                                                  \
            }                                                                  \
        }                                                                      \
        asm volatile("cp.async.commit_group;" ::: "memory");                   \
    }

    ISSUE(0);
    if (NC > 1) ISSUE(1);

    const int arow_in = lane & 15;
    const int akh     = lane >> 4;
    const int brow_in = ((lane >> 4) << 3) + (lane & 7);
    const int bkh     = (lane >> 3) & 1;

    for (int c = 0; c < NC; c++) {
        __syncthreads();
        if (c + 2 < NC) {
            ISSUE(c + 2);
            asm volatile("cp.async.wait_group 2;" ::: "memory");
        } else if (c + 1 < NC) {
            asm volatile("cp.async.wait_group 1;" ::: "memory");
        } else {
            asm volatile("cp.async.wait_group 0;" ::: "memory");
        }
        __syncthreads();

        const uint32_t st = sb + (c % NSTAGE) * STAGE_B;
#pragma unroll
        for (int kk = 0; kk < 2; kk++) {
            uint32_t aH[4][4], aL[4][4], bH[2][4], bL[2][4];
#pragma unroll
            for (int mi = 0; mi < 4; mi++) {
                const int row = wm * 64 + mi * 16 + arow_in;
                const uint32_t ad = st + swz(row, kk * 2 + akh);
                ldm4(aH[mi], ad);
                ldm4(aL[mi], ad + 8192);
            }
#pragma unroll
            for (int nj = 0; nj < 2; nj++) {
                const int row = wn * 32 + nj * 16 + brow_in;
                const uint32_t bd = st + 16384 + swz(row, kk * 2 + bkh);
                ldm4(bH[nj], bd);
                ldm4(bL[nj], bd + 8192);
            }
#pragma unroll
            for (int mi = 0; mi < 4; mi++)
#pragma unroll
                for (int ni = 0; ni < 4; ni++) {
                    const uint32_t* bh2 = &bH[ni >> 1][(ni & 1) * 2];
                    const uint32_t* bl2 = &bL[ni >> 1][(ni & 1) * 2];
                    mma16816(acc[mi][ni], aH[mi], bh2);
                    mma16816(acc[mi][ni], aH[mi], bl2);
                    mma16816(acc[mi][ni], aL[mi], bh2);
                }
        }
    }
    __syncthreads();
#undef ISSUE
}

static __device__ __forceinline__ void acc_to_smem(float (&acc)[4][4][4]) {
    extern __shared__ char smem[];
    float* ep = (float*)smem;
    const int lane = threadIdx.x & 31;
    const int wid  = threadIdx.x >> 5;
    const int wm = wid & 1, wn = wid >> 1;
#pragma unroll
    for (int mi = 0; mi < 4; mi++)
#pragma unroll
        for (int ni = 0; ni < 4; ni++) {
            const int r0 = wm * 64 + mi * 16 + (lane >> 2);
            const int c0 = wn * 32 + ni * 8 + (lane & 3) * 2;
            ep[r0 * EPI_STR + c0]           = acc[mi][ni][0];
            ep[r0 * EPI_STR + c0 + 1]       = acc[mi][ni][1];
            ep[(r0 + 8) * EPI_STR + c0]     = acc[mi][ni][2];
            ep[(r0 + 8) * EPI_STR + c0 + 1] = acc[mi][ni][3];
        }
    __syncthreads();
}

// ===================== fp32 -> bf16 hi/lo split ==============================
__global__ void __launch_bounds__(256)
cvt_kernel(const float* __restrict__ src, int which, int n) {
    __nv_bfloat16 *hi, *lo;
    switch (which) {
        case 0:  hi = g_xh;  lo = g_xl;  break;
        case 1:  hi = g_wqh; lo = g_wql; break;
        case 2:  hi = g_wkh; lo = g_wkl; break;
        case 3:  hi = g_wvh; lo = g_wvl; break;
        default: hi = g_wdh; lo = g_wdl; break;
    }
    int i0 = (blockIdx.x * 256 + threadIdx.x) * 4;
#pragma unroll
    for (int u = 0; u < 4; u++) {
        int i = i0 + u;
        if (i < n) split_bf(src[i], hi[i], lo[i]);
    }
}

// ===================== 1) QKV projection =====================================
__global__ void __launch_bounds__(256)
qkv_kernel(const float* __restrict__ pbq, const float* __restrict__ pbk,
           const float* __restrict__ pbv) {
    const int mode = blockIdx.z;
    const int m0 = blockIdx.y * 128, n0 = blockIdx.x * 128;
    const __nv_bfloat16* Wh = (mode == 0) ? g_wqh : (mode == 1) ? g_wkh : g_wvh;
    const __nv_bfloat16* Wl = (mode == 0) ? g_wql : (mode == 1) ? g_wkl : g_wvl;
    const float* bias = (mode == 0) ? pbq : (mode == 1) ? pbk : pbv;

    float acc[4][4][4] = {};
    mma_gemm(g_xh + (size_t)m0 * HIDDEN, g_xl + (size_t)m0 * HIDDEN,
             Wh + (size_t)n0 * HIDDEN, Wl + (size_t)n0 * HIDDEN,
             HIDDEN, HIDDEN, HIDDEN, acc);
    acc_to_smem(acc);

    extern __shared__ char smem[];
    const float* ep = (const float*)smem;
    const int tid = threadIdx.x;
    const int half = tid & 1;
    const int h = blockIdx.x;

    if (mode == 2) {
        const int dcol = tid >> 1;
        const int b = m0 >> 11;
        const float bia = bias[n0 + dcol];
        const size_t base = ((size_t)(b * NHEADS + h) * HDIM + dcol) * SEQ +
                            (m0 & (SEQ - 1)) + half * 64;
#pragma unroll 8
        for (int s = 0; s < 64; s += 2) {
            float v0 = ep[(half * 64 + s) * EPI_STR + dcol] + bia;
            float v1 = ep[(half * 64 + s + 1) * EPI_STR + dcol] + bia;
            __nv_bfloat16 h0, l0, h1, l1;
            split_bf(v0, h0, l0); split_bf(v1, h1, l1);
            *(__nv_bfloat162*)(g_vTh + base + s) = __nv_bfloat162(h0, h1);
            *(__nv_bfloat162*)(g_vTl + base + s) = __nv_bfloat162(l0, l1);
        }
    } else {
        const int r = tid >> 1;
        const int m = m0 + r;
        const int b = m >> 11, s = m & (SEQ - 1);
        __nv_bfloat16* dh = (mode == 0) ? g_qh : g_kh;
        __nv_bfloat16* dl = (mode == 0) ? g_ql : g_kl;
        const size_t base = ((size_t)(b * NHEADS + h) * SEQ + s) * HDIM + half * 64;
        const float* er = ep + r * EPI_STR + half * 64;
        const float* bi = bias + n0 + half * 64;
#pragma unroll 8
        for (int cc = 0; cc < 64; cc += 2) {
            float v0 = er[cc] + bi[cc];
            float v1 = er[cc + 1] + bi[cc + 1];
            __nv_bfloat16 h0, l0, h1, l1;
            split_bf(v0, h0, l0); split_bf(v1, h1, l1);
            *(__nv_bfloat162*)(dh + base + cc) = __nv_bfloat162(h0, h1);
            *(__nv_bfloat162*)(dl + base + cc) = __nv_bfloat162(l0, l1);
        }
    }
}

// ===================== 2) fused flash attention ==============================
// CTA: 128 q-rows of one (b,h). S=Q@K^T(+alibi) -> online softmax -> O+=P@V.
#define KBLK   64
#define NKB    (SEQ / KBLK)
#define FQ_H   0
#define FQ_L   32768
#define FSTG   65536                     // 2 stages x 64KB: Kh,Kl,Vh,Vl (16KB ea)
#define FP_H   196608
#define FP_L   (196608 + 16384)
#define FRED   229376                    // red_max[2][128], red_sum[2][128]
#define FSMEM  231424

__global__ void __launch_bounds__(256, 1)
flash_kernel(const float* __restrict__ alibi) {
    extern __shared__ char smem[];
    const uint32_t sb = s2u(smem);
    const int tid  = threadIdx.x;
    const int lane = tid & 31;
    const int wid  = tid >> 5;
    const int wm   = wid & 3;            // 4 row-slices of 32 q
    const int wn   = wid >> 2;           // 2 col-slices
    const int z    = blockIdx.y;
    const int m0   = blockIdx.x * 128;
    const size_t koff = (size_t)z * SEQ * HDIM;
    const size_t voff = (size_t)z * HDIM * SEQ;

    // ---- load Q hi/lo (group 0) ----
    {
        const int row = tid >> 1;
        const int c0  = (tid & 1) * 8;
        const char* gh = (const char*)(g_qh + koff + (size_t)(m0 + row) * HDIM);
        const char* gl = (const char*)(g_ql + koff + (size_t)(m0 + row) * HDIM);
#pragma unroll
        for (int u = 0; u < 8; u++) {
            uint32_t so = swz256(row, c0 + u);
            cpa16(sb + FQ_H + so, gh + (c0 + u) * 16);
            cpa16(sb + FQ_L + so, gl + (c0 + u) * 16);
        }
        asm volatile("cp.async.commit_group;" ::: "memory");
    }

#define FISSUE(kb_)                                                            \
    {                                                                          \
        const int _kb = (kb_);                                                 \
        const uint32_t stg_ = sb + FSTG + (_kb & 1) * 65536;                   \
        {                                                                      \
            const int row = tid >> 2; const int c0 = (tid & 3) * 4;            \
            const char* gh = (const char*)(g_kh + koff +                       \
                                           (size_t)(_kb * KBLK + row) * HDIM); \
            const char* gl = (const char*)(g_kl + koff +                       \
                                           (size_t)(_kb * KBLK + row) * HDIM); \
            _Pragma("unroll")                                                  \
            for (int u = 0; u < 4; u++) {                                      \
                uint32_t so = swz256(row, c0 + u);                             \
                cpa16(stg_ + so,         gh + (c0 + u) * 16);                  \
                cpa16(stg_ + 16384 + so, gl + (c0 + u) * 16);                  \
            }                                                                  \
        }                                                                      \
        {                                                                      \
            const int row = tid >> 1; const int c0 = (tid & 1) * 4;            \
            const char* gh = (const char*)(g_vTh + voff + (size_t)row * SEQ +  \
                                           _kb * KBLK);                        \
            const char* gl = (const char*)(g_vTl + voff + (size_t)row * SEQ +  \
                                           _kb * KBLK);                        \
            _Pragma("unroll")                                                  \
            for (int u = 0; u < 4; u++) {                                      \
                uint32_t so = swz128(row, c0 + u);                             \
                cpa16(stg_ + 32768 + so, gh + (c0 + u) * 16);                  \
                cpa16(stg_ + 49152 + so, gl + (c0 + u) * 16);                  \
            }                                                                  \
        }                                                                      \
        asm volatile("cp.async.commit_group;" ::: "memory");                   \
    }

    FISSUE(0);

    const int arow_in = lane & 15;
    const int akh     = lane >> 4;
    const int brow_in = ((lane >> 4) << 3) + (lane & 7);
    const int bkh     = (lane >> 3) & 1;
    const int qr      = lane >> 2;       // 0..7
    const int qc      = (lane & 3) * 2;  // 0..6

    float m_r[4], l_r[4], acc_o[2][8][4];
#pragma unroll
    for (int i = 0; i < 4; i++) { m_r[i] = -INFINITY; l_r[i] = 0.f; }
#pragma unroll
    for (int mi = 0; mi < 2; mi++)
#pragma unroll
        for (int ni = 0; ni < 8; ni++)
#pragma unroll
            for (int e = 0; e < 4; e++) acc_o[mi][ni][e] = 0.f;

    float* redm = (float*)(smem + FRED);
    float* reds = (float*)(smem + FRED + 1024);

    for (int kb = 0; kb < NKB; kb++) {
        if (kb + 1 < NKB) {
            FISSUE(kb + 1);
            asm volatile("cp.async.wait_group 1;" ::: "memory");
        } else {
            asm volatile("cp.async.wait_group 0;" ::: "memory");
        }
        __syncthreads();
        const uint32_t stg = sb + FSTG + (kb & 1) * 65536;

        // ---- S = Q @ K^T : warp tile 32q x 32k, k-dim = d = 128 ----
        float acc_s[2][4][4] = {};
#pragma unroll
        for (int ks = 0; ks < 8; ks++) {
            uint32_t aH[2][4], aL[2][4], bH[2][4], bL[2][4];
#pragma unroll
            for (int mi = 0; mi < 2; mi++) {
                const int row = wm * 32 + mi * 16 + arow_in;
                const uint32_t ad = swz256(row, ks * 2 + akh);
                ldm4(aH[mi], sb + FQ_H + ad);
                ldm4(aL[mi], sb + FQ_L + ad);
            }
#pragma unroll
            for (int nj = 0; nj < 2; nj++) {
                const int row = wn * 32 + nj * 16 + brow_in;
                const uint32_t bd = swz256(row, ks * 2 + bkh);
                ldm4(bH[nj], stg + bd);
                ldm4(bL[nj], stg + 16384 + bd);
            }
#pragma unroll
            for (int mi = 0; mi < 2; mi++)
#pragma unroll
                for (int ni = 0; ni < 4; ni++) {
                    const uint32_t* bh2 = &bH[ni >> 1][(ni & 1) * 2];
                    const uint32_t* bl2 = &bL[ni >> 1][(ni & 1) * 2];
                    mma16816(acc_s[mi][ni], aH[mi], bh2);
                    mma16816(acc_s[mi][ni], aH[mi], bl2);
                    mma16816(acc_s[mi][ni], aL[mi], bh2);
                }
        }

        // ---- scores + online softmax ----
        float alv[4][2];
        {
            const float* al = alibi + (size_t)z * SEQ + kb * KBLK + wn * 32;
#pragma unroll
            for (int ni = 0; ni < 4; ni++) {
                alv[ni][0] = al[ni * 8 + qc];
                alv[ni][1] = al[ni * 8 + qc + 1];
            }
        }
        float sc[2][4][4];
#pragma unroll
        for (int mi = 0; mi < 2; mi++)
#pragma unroll
            for (int ni = 0; ni < 4; ni++)
#pragma unroll
                for (int e = 0; e < 4; e++)
                    sc[mi][ni][e] = alv[ni][e & 1] + INV_NORM * acc_s[mi][ni][e];

        float tmax[4];
#pragma unroll
        for (int i = 0; i < 4; i++) tmax[i] = -INFINITY;
#pragma unroll
        for (int mi = 0; mi < 2; mi++)
#pragma unroll
            for (int ni = 0; ni < 4; ni++) {
                tmax[mi * 2]     = fmaxf(tmax[mi * 2],
                                         fmaxf(sc[mi][ni][0], sc[mi][ni][1]));
                tmax[mi * 2 + 1] = fmaxf(tmax[mi * 2 + 1],
                                         fmaxf(sc[mi][ni][2], sc[mi][ni][3]));
            }
#pragma unroll
        for (int i = 0; i < 4; i++) {
            tmax[i] = fmaxf(tmax[i], __shfl_xor_sync(0xffffffffu, tmax[i], 1));
            tmax[i] = fmaxf(tmax[i], __shfl_xor_sync(0xffffffffu, tmax[i], 2));
        }
        if ((lane & 3) == 0) {
#pragma unroll
            for (int i = 0; i < 4; i++) {
                const int r = wm * 32 + (i >> 1) * 16 + qr + (i & 1) * 8;
                redm[wn * 128 + r] = tmax[i];
            }
        }
        __syncthreads();

        float fct[4];
#pragma unroll
        for (int i = 0; i < 4; i++) {
            const int r = wm * 32 + (i >> 1) * 16 + qr + (i & 1) * 8;
            const float mnew = fmaxf(m_r[i], fmaxf(redm[r], redm[128 + r]));
            fct[i] = __expf(m_r[i] - mnew);
            m_r[i] = mnew;
        }

        float tsum[4] = {0.f, 0.f, 0.f, 0.f};
#pragma unroll
        for (int mi = 0; mi < 2; mi++)
#pragma unroll
            for (int ni = 0; ni < 4; ni++)
#pragma unroll
                for (int e = 0; e < 4; e++) {
                    const int i = mi * 2 + (e >> 1);
                    const float p = __expf(sc[mi][ni][e] - m_r[i]);
                    sc[mi][ni][e] = p;
                    tsum[i] += p;
                }
#pragma unroll
        for (int i = 0; i < 4; i++) {
            tsum[i] += __shfl_xor_sync(0xffffffffu, tsum[i], 1);
            tsum[i] += __shfl_xor_sync(0xffffffffu, tsum[i], 2);
        }
        if ((lane & 3) == 0) {
#pragma unroll
            for (int i = 0; i < 4; i++) {
                const int r = wm * 32 + (i >> 1) * 16 + qr + (i & 1) * 8;
                reds[wn * 128 + r] = tsum[i];
            }
        }

        // ---- P -> smem (hi/lo) ----
#pragma unroll
        for (int mi = 0; mi < 2; mi++)
#pragma unroll
            for (int ni = 0; ni < 4; ni++)
#pragma unroll
                for (int h2 = 0; h2 < 2; h2++) {
                    const int row  = wm * 32 + mi * 16 + qr + h2 * 8;
                    const int colb = wn * 64 + ni * 16 + (lane & 3) * 4;
                    const uint32_t so = (uint32_t)(row * 128 +
                        (((colb >> 4) ^ (row & 7)) << 4) + (colb & 15));
                    __nv_bfloat16 h0, l0, h1, l1;
                    split_bf(sc[mi][ni][h2 * 2],     h0, l0);
                    split_bf(sc[mi][ni][h2 * 2 + 1], h1, l1);
                    *(__nv_bfloat162*)(smem + FP_H + so) = __nv_bfloat162(h0, h1);
                    *(__nv_bfloat162*)(smem + FP_L + so) = __nv_bfloat162(l0, l1);
                }
        __syncthreads();

#pragma unroll
        for (int i = 0; i < 4; i++) {
            const int r = wm * 32 + (i >> 1) * 16 + qr + (i & 1) * 8;
            l_r[i] = l_r[i] * fct[i] + reds[r] + reds[128 + r];
        }
#pragma unroll
        for (int mi = 0; mi < 2; mi++)
#pragma unroll
            for (int ni = 0; ni < 8; ni++)
#pragma unroll
                for (int e = 0; e < 4; e++)
                    acc_o[mi][ni][e] *= fct[mi * 2 + (e >> 1)];

        // ---- O += P @ V : warp tile 32q x 64d, k-dim = s = 64 ----
#pragma unroll
        for (int ks = 0; ks < 4; ks++) {
            uint32_t pH[2][4], pL[2][4], vH[4][4], vL[4][4];
#pragma unroll
            for (int mi = 0; mi < 2; mi++) {
                const int row = wm * 32 + mi * 16 + arow_in;
                const uint32_t ad = swz128(row, ks * 2 + akh);
                ldm4(pH[mi], sb + FP_H + ad);
                ldm4(pL[mi], sb + FP_L + ad);
            }
#pragma unroll
            for (int nj = 0; nj < 4; nj++) {
                const int row = wn * 64 + nj * 16 + brow_in;
                const uint32_t bd = swz128(row, ks * 2 + bkh);
                ldm4(vH[nj], stg + 32768 + bd);
                ldm4(vL[nj], stg + 49152 + bd);
            }
#pragma unroll
            for (int mi = 0; mi < 2; mi++)
#pragma unroll
                for (int ni = 0; ni < 8; ni++) {
                    const uint32_t* vh2 = &vH[ni >> 1][(ni & 1) * 2];
                    const uint32_t* vl2 = &vL[ni >> 1][(ni & 1) * 2];
                    mma16816(acc_o[mi][ni], pH[mi], vh2);
                    mma16816(acc_o[mi][ni], pH[mi], vl2);
                    mma16816(acc_o[mi][ni], pL[mi], vh2);
                }
        }
        __syncthreads();
    }
#undef FISSUE

    // ---- epilogue: O / l -> ctx hi/lo ----
    const int b = z / NHEADS;
    const int hh = z % NHEADS;
#pragma unroll
    for (int mi = 0; mi < 2; mi++)
#pragma unroll
        for (int h2 = 0; h2 < 2; h2++) {
            const int i = mi * 2 + h2;
            const float inv = 1.0f / l_r[i];
            const int row = wm * 32 + mi * 16 + qr + h2 * 8;
            const size_t base = ((size_t)(b * SEQ) + m0 + row) * HIDDEN +
                                hh * HDIM;
#pragma unroll
            for (int ni = 0; ni < 8; ni++) {
                const int col = wn * 64 + ni * 8 + qc;
                const float v0 = acc_o[mi][ni][h2 * 2] * inv;
                const float v1 = acc_o[mi][ni][h2 * 2 + 1] * inv;
                __nv_bfloat16 h0, l0, h1, l1;
                split_bf(v0, h0, l0);
                split_bf(v1, h1, l1);
                *(__nv_bfloat162*)(g_ch + base + col) = __nv_bfloat162(h0, h1);
                *(__nv_bfloat162*)(g_cl + base + col) = __nv_bfloat162(l0, l1);
            }
        }
}

// ===================== 3) out = ctx @ Wd^T + bd + residual ===================
__global__ void __launch_bounds__(256)
out_kernel(const float* __restrict__ bd, const float* __restrict__ residual,
           float* __restrict__ outp) {
    const int m0 = blockIdx.y * 128, n0 = blockIdx.x * 128;

    float acc[4][4][4] = {};
    mma_gemm(g_ch + (size_t)m0 * HIDDEN, g_cl + (size_t)m0 * HIDDEN,
             g_wdh + (size_t)n0 * HIDDEN, g_wdl + (size_t)n0 * HIDDEN,
             HIDDEN, HIDDEN, HIDDEN, acc);
    acc_to_smem(acc);

    extern __shared__ char smem[];
    const float* ep = (const float*)smem;
    const int tid = threadIdx.x;
    const int r = tid >> 1, half = tid & 1;
    const size_t idx = (size_t)(m0 + r) * HIDDEN + n0 + half * 64;
    const float* er = ep + r * EPI_STR + half * 64;
    const float* bi = bd + n0 + half * 64;
    const float* rs = residual + idx;
    float* dst = outp + idx;
#pragma unroll 4
    for (int cc = 0; cc < 64; cc += 4) {
        float4 bv = *(const float4*)(bi + cc);
        float4 rv = *(const float4*)(rs + cc);
        float4 v;
        v.x = er[cc + 0] + bv.x + rv.x;
        v.y = er[cc + 1] + bv.y + rv.y;
        v.z = er[cc + 2] + bv.z + rv.z;
        v.w = er[cc + 3] + bv.w + rv.w;
        *(float4*)(dst + cc) = v;
    }
}

// ===================== launch =================================================
extern "C" void kernel_launch(void* const* d_in, const int* in_sizes, int n_in,
                              void* d_out, int out_size) {
    const float* X        = (const float*)d_in[0];
    const float* residual = (const float*)d_in[1];
    const float* alibi    = (const float*)d_in[2];
    const float* Wq = (const float*)d_in[3];  const float* bq = (const float*)d_in[4];
    const float* Wk = (const float*)d_in[5];  const float* bk = (const float*)d_in[6];
    const float* Wv = (const float*)d_in[7];  const float* bv = (const float*)d_in[8];
    const float* Wd = (const float*)d_in[9];  const float* bd = (const float*)d_in[10];
    float* out = (float*)d_out;

    cudaFuncSetAttribute(qkv_kernel, cudaFuncAttributeMaxDynamicSharedMemorySize, SMEM_DYN);
    cudaFuncSetAttribute(out_kernel, cudaFuncAttributeMaxDynamicSharedMemorySize, SMEM_DYN);
    cudaFuncSetAttribute(flash_kernel, cudaFuncAttributeMaxDynamicSharedMemorySize, FSMEM);

    dim3 blk(256);
    const int nX = MROWS * HIDDEN;
    const int nW = HIDDEN * HIDDEN;
    cvt_kernel<<<nX / 1024, blk>>>(X,  0, nX);
    cvt_kernel<<<nW / 1024, blk>>>(Wq, 1, nW);
    cvt_kernel<<<nW / 1024, blk>>>(Wk, 2, nW);
    cvt_kernel<<<nW / 1024, blk>>>(Wv, 3, nW);
    cvt_kernel<<<nW / 1024, blk>>>(Wd, 4, nW);

    qkv_kernel<<<dim3(16, 32, 3), blk, SMEM_DYN>>>(bq, bk, bv);
    flash_kernel<<<dim3(16, 32), blk, FSMEM>>>(alibi);
    out_kernel<<<dim3(16, 32), blk, SMEM_DYN>>>(bd, residual, out);
}

// round 5
// speedup vs baseline: 1.5532x; 1.5532x over previous
#include <cuda_runtime.h>
#include <cuda_bf16.h>
#include <math.h>
#include <stdint.h>

#define HIDDEN   2048
#define NHEADS   16
#define HDIM     128
#define BATCH    2
#define SEQ      2048
#define BH       (BATCH * NHEADS)
#define MROWS    (BATCH * SEQ)
#define INV_NORM 0.08838834764831845f   // 1/sqrt(128)

#define KB        32
#define STAGE_B   32768
#define NSTAGE    3
#define EPI_STR   132
#define SMEM_DYN  (NSTAGE * STAGE_B)     // 96KB

// ===================== scratch (static __device__, no allocation) ============
__device__ __align__(128) float g_scores[(size_t)BH * SEQ * SEQ];   // 512MB
__device__ __align__(128) float g_rmax[(size_t)BH * SEQ];
__device__ __align__(128) float g_rinv[(size_t)BH * SEQ];

__device__ __align__(128) __nv_bfloat16 g_xh[(size_t)MROWS * HIDDEN];
__device__ __align__(128) __nv_bfloat16 g_xl[(size_t)MROWS * HIDDEN];
__device__ __align__(128) __nv_bfloat16 g_wqh[(size_t)HIDDEN * HIDDEN];
__device__ __align__(128) __nv_bfloat16 g_wql[(size_t)HIDDEN * HIDDEN];
__device__ __align__(128) __nv_bfloat16 g_wkh[(size_t)HIDDEN * HIDDEN];
__device__ __align__(128) __nv_bfloat16 g_wkl[(size_t)HIDDEN * HIDDEN];
__device__ __align__(128) __nv_bfloat16 g_wvh[(size_t)HIDDEN * HIDDEN];
__device__ __align__(128) __nv_bfloat16 g_wvl[(size_t)HIDDEN * HIDDEN];
__device__ __align__(128) __nv_bfloat16 g_wdh[(size_t)HIDDEN * HIDDEN];
__device__ __align__(128) __nv_bfloat16 g_wdl[(size_t)HIDDEN * HIDDEN];

__device__ __align__(128) __nv_bfloat16 g_qh[(size_t)BH * SEQ * HDIM];
__device__ __align__(128) __nv_bfloat16 g_ql[(size_t)BH * SEQ * HDIM];
__device__ __align__(128) __nv_bfloat16 g_kh[(size_t)BH * SEQ * HDIM];
__device__ __align__(128) __nv_bfloat16 g_kl[(size_t)BH * SEQ * HDIM];
__device__ __align__(128) __nv_bfloat16 g_vTh[(size_t)BH * HDIM * SEQ];
__device__ __align__(128) __nv_bfloat16 g_vTl[(size_t)BH * HDIM * SEQ];
__device__ __align__(128) __nv_bfloat16 g_ch[(size_t)MROWS * HIDDEN];
__device__ __align__(128) __nv_bfloat16 g_cl[(size_t)MROWS * HIDDEN];

// ===================== helpers ===============================================
static __device__ __forceinline__ uint32_t s2u(const void* p) {
    uint32_t a;
    asm("{ .reg .u64 t; cvta.to.shared.u64 t, %1; cvt.u32.u64 %0, t; }"
        : "=r"(a) : "l"(p));
    return a;
}
static __device__ __forceinline__ void ldm4(uint32_t (&r)[4], uint32_t addr) {
    asm volatile("ldmatrix.sync.aligned.m8n8.x4.shared.b16 {%0,%1,%2,%3}, [%4];"
                 : "=r"(r[0]), "=r"(r[1]), "=r"(r[2]), "=r"(r[3]) : "r"(addr));
}
static __device__ __forceinline__ void mma16816(float (&c)[4],
                                                const uint32_t (&a)[4],
                                                const uint32_t* b) {
    asm volatile("mma.sync.aligned.m16n8k16.row.col.f32.bf16.bf16.f32 "
                 "{%0,%1,%2,%3}, {%4,%5,%6,%7}, {%8,%9}, {%0,%1,%2,%3};"
                 : "+f"(c[0]), "+f"(c[1]), "+f"(c[2]), "+f"(c[3])
                 : "r"(a[0]), "r"(a[1]), "r"(a[2]), "r"(a[3]),
                   "r"(b[0]), "r"(b[1]));
}
static __device__ __forceinline__ void split_bf(float x, __nv_bfloat16& h,
                                                __nv_bfloat16& l) {
    h = __float2bfloat16(x);
    l = __float2bfloat16(x - __bfloat162float(h));
}
static __device__ __forceinline__ void cpa16(uint32_t so, const void* g) {
    asm volatile("cp.async.cg.shared.global [%0], [%1], 16;" :: "r"(so), "l"(g));
}
static __device__ __forceinline__ uint32_t swz(int row, int c16) {       // 64B rows
    return (uint32_t)(row * 64 + ((c16 ^ ((row >> 1) & 3)) << 4));
}
static __device__ __forceinline__ uint32_t swz128(int row, int c16) {    // 128B rows
    return (uint32_t)(row * 128 + ((c16 ^ (row & 7)) << 4));
}

// ===================== bf16x3 mma.sync GEMM core (projections/scores) ========
static __device__ __forceinline__ void mma_gemm(
    const __nv_bfloat16* __restrict__ Ah, const __nv_bfloat16* __restrict__ Al,
    const __nv_bfloat16* __restrict__ Bh, const __nv_bfloat16* __restrict__ Bl,
    int K, int lda, int ldb, float (&acc)[4][4][4]) {
    extern __shared__ char smem[];
    const uint32_t sb = s2u(smem);
    const int tid  = threadIdx.x;
    const int lane = tid & 31;
    const int wid  = tid >> 5;
    const int wm   = wid & 1;
    const int wn   = wid >> 1;
    const int NC   = K >> 5;

    const __nv_bfloat16* srcs[4] = { Ah, Al, Bh, Bl };
    const int lds[4] = { lda, lda, ldb, ldb };
    const int lrow = tid >> 2;
    const int lc16 = tid & 3;

#define ISSUE(cc)                                                              \
    {                                                                          \
        const int _c = (cc);                                                   \
        const uint32_t sbase = sb + (_c % NSTAGE) * STAGE_B;                   \
        _Pragma("unroll")                                                      \
        for (int mat = 0; mat < 4; mat++) {                                    \
            _Pragma("unroll")                                                  \
            for (int rep = 0; rep < 2; rep++) {                                \
                const int row = lrow + rep * 64;                               \
                const char* g = (const char*)(srcs[mat] +                      \
                                  (size_t)row * lds[mat] + _c * KB) + lc16*16; \
                const uint32_t so = sbase + mat * 8192 + swz(row, lc16);       \
                cpa16(so, g);                                                  \
            }                                                                  \
        }                                                                      \
        asm volatile("cp.async.commit_group;" ::: "memory");                   \
    }

    ISSUE(0);
    if (NC > 1) ISSUE(1);

    const int arow_in = lane & 15;
    const int akh     = lane >> 4;
    const int brow_in = ((lane >> 4) << 3) + (lane & 7);
    const int bkh     = (lane >> 3) & 1;

    for (int c = 0; c < NC; c++) {
        if (c + 1 < NC) {
            asm volatile("cp.async.wait_group 1;" ::: "memory");
        } else {
            asm volatile("cp.async.wait_group 0;" ::: "memory");
        }
        __syncthreads();          // stage c visible; everyone done with c-1

        const uint32_t st = sb + (c % NSTAGE) * STAGE_B;
#pragma unroll
        for (int kk = 0; kk < 2; kk++) {
            uint32_t aH[4][4], aL[4][4], bH[2][4], bL[2][4];
#pragma unroll
            for (int mi = 0; mi < 4; mi++) {
                const int row = wm * 64 + mi * 16 + arow_in;
                const uint32_t ad = st + swz(row, kk * 2 + akh);
                ldm4(aH[mi], ad);
                ldm4(aL[mi], ad + 8192);
            }
#pragma unroll
            for (int nj = 0; nj < 2; nj++) {
                const int row = wn * 32 + nj * 16 + brow_in;
                const uint32_t bd = st + 16384 + swz(row, kk * 2 + bkh);
                ldm4(bH[nj], bd);
                ldm4(bL[nj], bd + 8192);
            }
#pragma unroll
            for (int mi = 0; mi < 4; mi++)
#pragma unroll
                for (int ni = 0; ni < 4; ni++) {
                    const uint32_t* bh2 = &bH[ni >> 1][(ni & 1) * 2];
                    const uint32_t* bl2 = &bL[ni >> 1][(ni & 1) * 2];
                    mma16816(acc[mi][ni], aH[mi], bh2);
                    mma16816(acc[mi][ni], aH[mi], bl2);
                    mma16816(acc[mi][ni], aL[mi], bh2);
                }
        }
        if (c + 2 < NC) ISSUE(c + 2);   // stage (c-1)%3 is free (post-barrier)
    }
    __syncthreads();
#undef ISSUE
}

static __device__ __forceinline__ void acc_to_smem(float (&acc)[4][4][4]) {
    extern __shared__ char smem[];
    float* ep = (float*)smem;
    const int lane = threadIdx.x & 31;
    const int wid  = threadIdx.x >> 5;
    const int wm = wid & 1, wn = wid >> 1;
#pragma unroll
    for (int mi = 0; mi < 4; mi++)
#pragma unroll
        for (int ni = 0; ni < 4; ni++) {
            const int r0 = wm * 64 + mi * 16 + (lane >> 2);
            const int c0 = wn * 32 + ni * 8 + (lane & 3) * 2;
            ep[r0 * EPI_STR + c0]           = acc[mi][ni][0];
            ep[r0 * EPI_STR + c0 + 1]       = acc[mi][ni][1];
            ep[(r0 + 8) * EPI_STR + c0]     = acc[mi][ni][2];
            ep[(r0 + 8) * EPI_STR + c0 + 1] = acc[mi][ni][3];
        }
    __syncthreads();
}

// ===================== fp32 -> bf16 hi/lo split (vectorized) =================
__global__ void __launch_bounds__(256)
cvt_kernel(const float* __restrict__ src, int which, int n4) {
    __nv_bfloat16 *hi, *lo;
    switch (which) {
        case 0:  hi = g_xh;  lo = g_xl;  break;
        case 1:  hi = g_wqh; lo = g_wql; break;
        case 2:  hi = g_wkh; lo = g_wkl; break;
        case 3:  hi = g_wvh; lo = g_wvl; break;
        default: hi = g_wdh; lo = g_wdl; break;
    }
    const int i = blockIdx.x * 256 + threadIdx.x;
    if (i < n4) {
        float4 v = ((const float4*)src)[i];
        __nv_bfloat16 h0, l0, h1, l1, h2, l2, h3, l3;
        split_bf(v.x, h0, l0); split_bf(v.y, h1, l1);
        split_bf(v.z, h2, l2); split_bf(v.w, h3, l3);
        __nv_bfloat162 hv[2] = { __nv_bfloat162(h0, h1), __nv_bfloat162(h2, h3) };
        __nv_bfloat162 lv[2] = { __nv_bfloat162(l0, l1), __nv_bfloat162(l2, l3) };
        *(uint2*)(hi + (size_t)i * 4) = *(uint2*)hv;
        *(uint2*)(lo + (size_t)i * 4) = *(uint2*)lv;
    }
}

// ===================== 1) QKV projection =====================================
__global__ void __launch_bounds__(256, 2)
qkv_kernel(const float* __restrict__ pbq, const float* __restrict__ pbk,
           const float* __restrict__ pbv) {
    const int mode = blockIdx.z;
    const int m0 = blockIdx.y * 128, n0 = blockIdx.x * 128;
    const __nv_bfloat16* Wh = (mode == 0) ? g_wqh : (mode == 1) ? g_wkh : g_wvh;
    const __nv_bfloat16* Wl = (mode == 0) ? g_wql : (mode == 1) ? g_wkl : g_wvl;
    const float* bias = (mode == 0) ? pbq : (mode == 1) ? pbk : pbv;

    float acc[4][4][4] = {};
    mma_gemm(g_xh + (size_t)m0 * HIDDEN, g_xl + (size_t)m0 * HIDDEN,
             Wh + (size_t)n0 * HIDDEN, Wl + (size_t)n0 * HIDDEN,
             HIDDEN, HIDDEN, HIDDEN, acc);
    acc_to_smem(acc);

    extern __shared__ char smem[];
    const float* ep = (const float*)smem;
    const int tid = threadIdx.x;
    const int half = tid & 1;
    const int h = blockIdx.x;

    if (mode == 2) {
        const int dcol = tid >> 1;
        const int b = m0 >> 11;
        const float bia = bias[n0 + dcol];
        const size_t base = ((size_t)(b * NHEADS + h) * HDIM + dcol) * SEQ +
                            (m0 & (SEQ - 1)) + half * 64;
#pragma unroll 8
        for (int s = 0; s < 64; s += 2) {
            float v0 = ep[(half * 64 + s) * EPI_STR + dcol] + bia;
            float v1 = ep[(half * 64 + s + 1) * EPI_STR + dcol] + bia;
            __nv_bfloat16 h0, l0, h1, l1;
            split_bf(v0, h0, l0); split_bf(v1, h1, l1);
            *(__nv_bfloat162*)(g_vTh + base + s) = __nv_bfloat162(h0, h1);
            *(__nv_bfloat162*)(g_vTl + base + s) = __nv_bfloat162(l0, l1);
        }
    } else {
        const int r = tid >> 1;
        const int m = m0 + r;
        const int b = m >> 11, s = m & (SEQ - 1);
        __nv_bfloat16* dh = (mode == 0) ? g_qh : g_kh;
        __nv_bfloat16* dl = (mode == 0) ? g_ql : g_kl;
        const size_t base = ((size_t)(b * NHEADS + h) * SEQ + s) * HDIM + half * 64;
        const float* er = ep + r * EPI_STR + half * 64;
        const float* bi = bias + n0 + half * 64;
#pragma unroll 8
        for (int cc = 0; cc < 64; cc += 2) {
            float v0 = er[cc] + bi[cc];
            float v1 = er[cc + 1] + bi[cc + 1];
            __nv_bfloat16 h0, l0, h1, l1;
            split_bf(v0, h0, l0); split_bf(v1, h1, l1);
            *(__nv_bfloat162*)(dh + base + cc) = __nv_bfloat162(h0, h1);
            *(__nv_bfloat162*)(dl + base + cc) = __nv_bfloat162(l0, l1);
        }
    }
}

// ===================== 2) scores = alibi + inv_norm * Q K^T ==================
__global__ void __launch_bounds__(256, 2)
scores_kernel(const float* __restrict__ alibi) {
    const int z = blockIdx.z;
    const int m0 = blockIdx.y * 128, n0 = blockIdx.x * 128;
    const size_t zo = (size_t)z * SEQ * HDIM;

    float acc[4][4][4] = {};
    mma_gemm(g_qh + zo + (size_t)m0 * HDIM, g_ql + zo + (size_t)m0 * HDIM,
             g_kh + zo + (size_t)n0 * HDIM, g_kl + zo + (size_t)n0 * HDIM,
             HDIM, HDIM, HDIM, acc);
    acc_to_smem(acc);

    extern __shared__ char smem[];
    const float* ep = (const float*)smem;
    const int tid = threadIdx.x;
    const int r = tid >> 1, half = tid & 1;
    const float* al = alibi + (size_t)z * SEQ + n0 + half * 64;
    float* C = g_scores + (size_t)z * SEQ * SEQ +
               (size_t)(m0 + r) * SEQ + n0 + half * 64;
    const float* er = ep + r * EPI_STR + half * 64;
#pragma unroll 4
    for (int cc = 0; cc < 64; cc += 4) {
        float4 av = *(const float4*)(al + cc);
        float4 v;
        v.x = av.x + INV_NORM * er[cc + 0];
        v.y = av.y + INV_NORM * er[cc + 1];
        v.z = av.z + INV_NORM * er[cc + 2];
        v.w = av.w + INV_NORM * er[cc + 3];
        *(float4*)(C + cc) = v;
    }
}

// ===================== 3) row stats (max, 1/sum) =============================
__global__ void __launch_bounds__(256)
stats_kernel() {
    const size_t ro = (size_t)blockIdx.x * SEQ;
    const float* p = g_scores + ro;
    const int tid = threadIdx.x;
    __shared__ float red[256];

    float vals[8];
    float lmax = -INFINITY;
#pragma unroll
    for (int i = 0; i < 8; i++) {
        vals[i] = p[tid + i * 256];
        lmax = fmaxf(lmax, vals[i]);
    }
    red[tid] = lmax;
    __syncthreads();
    for (int s = 128; s > 0; s >>= 1) {
        if (tid < s) red[tid] = fmaxf(red[tid], red[tid + s]);
        __syncthreads();
    }
    const float rmax = red[0];
    __syncthreads();

    float lsum = 0.f;
#pragma unroll
    for (int i = 0; i < 8; i++) lsum += __expf(vals[i] - rmax);
    red[tid] = lsum;
    __syncthreads();
    for (int s = 128; s > 0; s >>= 1) {
        if (tid < s) red[tid] += red[tid + s];
        __syncthreads();
    }
    if (tid == 0) {
        g_rmax[blockIdx.x] = rmax;
        g_rinv[blockIdx.x] = 1.0f / red[0];
    }
}

// ===================== 4) ctx = softmax(S) @ V (exp fused) ===================
// stage layout: S fp32 16K | Ah 8K | Al 8K | Bh 8K | Bl 8K = 48K, 2 stages
#define CST_S   0
#define CST_AH  16384
#define CST_AL  24576
#define CST_BH  32768
#define CST_BL  40960
#define CSTG_B  49152
#define CSMEM   (2 * CSTG_B)     // 98304

__global__ void __launch_bounds__(256, 2)
ctx_kernel() {
    extern __shared__ char smem[];
    const uint32_t sb = s2u(smem);
    const int tid  = threadIdx.x;
    const int lane = tid & 31;
    const int wid  = tid >> 5;
    const int wm   = wid & 1;
    const int wn   = wid >> 1;
    const int z    = blockIdx.z;
    const int m0   = blockIdx.y * 128;
    const size_t so_base = (size_t)z * SEQ * SEQ + (size_t)m0 * SEQ;
    const size_t vo = (size_t)z * HDIM * SEQ;
    const int NC = SEQ / 32;     // 64

    const int crow = tid >> 1;           // loader/convert row 0..127
    const int chf  = tid & 1;
    const float rmaxv = g_rmax[(size_t)z * SEQ + m0 + crow];
    const float rinvv = g_rinv[(size_t)z * SEQ + m0 + crow];

#define CISSUE(cc)                                                             \
    {                                                                          \
        const int _c = (cc);                                                   \
        const uint32_t sbase = sb + (_c & 1) * CSTG_B;                         \
        const char* gs = (const char*)(g_scores + so_base +                    \
                                       (size_t)crow * SEQ) + _c * 128;         \
        _Pragma("unroll")                                                      \
        for (int u = 0; u < 4; u++) {                                          \
            const int c16 = chf * 4 + u;                                       \
            cpa16(sbase + CST_S + swz128(crow, c16), gs + c16 * 16);           \
        }                                                                      \
        const char* gvh = (const char*)(g_vTh + vo + (size_t)crow * SEQ) +     \
                          _c * 64;                                             \
        const char* gvl = (const char*)(g_vTl + vo + (size_t)crow * SEQ) +     \
                          _c * 64;                                             \
        _Pragma("unroll")                                                      \
        for (int u = 0; u < 2; u++) {                                          \
            const int c16 = chf * 2 + u;                                       \
            cpa16(sbase + CST_BH + swz(crow, c16), gvh + c16 * 16);            \
            cpa16(sbase + CST_BL + swz(crow, c16), gvl + c16 * 16);            \
        }                                                                      \
        asm volatile("cp.async.commit_group;" ::: "memory");                   \
    }

    CISSUE(0);

    const int arow_in = lane & 15;
    const int akh     = lane >> 4;
    const int brow_in = ((lane >> 4) << 3) + (lane & 7);
    const int bkh     = (lane >> 3) & 1;

    float acc[4][4][4] = {};

    for (int c = 0; c < NC; c++) {
        asm volatile("cp.async.wait_group 0;" ::: "memory");
        __syncthreads();                    // stage c data visible, c-1 done
        const uint32_t stg = sb + (c & 1) * CSTG_B;
        if (c + 1 < NC) CISSUE(c + 1);      // other buffer: free post-barrier

        // ---- convert S -> P hi/lo in A-tile layout ----
#pragma unroll
        for (int u = 0; u < 4; u++) {
            const int c16 = chf * 4 + u;
            float4 s = *(const float4*)(smem + (c & 1) * CSTG_B + CST_S +
                                        swz128(crow, c16));
            float p0 = __expf(s.x - rmaxv) * rinvv;
            float p1 = __expf(s.y - rmaxv) * rinvv;
            float p2 = __expf(s.z - rmaxv) * rinvv;
            float p3 = __expf(s.w - rmaxv) * rinvv;
            __nv_bfloat16 h0, l0, h1, l1, h2, l2, h3, l3;
            split_bf(p0, h0, l0); split_bf(p1, h1, l1);
            split_bf(p2, h2, l2); split_bf(p3, h3, l3);
            __nv_bfloat162 hv[2] = { __nv_bfloat162(h0, h1),
                                     __nv_bfloat162(h2, h3) };
            __nv_bfloat162 lv[2] = { __nv_bfloat162(l0, l1),
                                     __nv_bfloat162(l2, l3) };
            const uint32_t da = (c & 1) * CSTG_B + swz(crow, c16 >> 1) +
                                (c16 & 1) * 8;
            *(uint2*)(smem + da + CST_AH) = *(uint2*)hv;
            *(uint2*)(smem + da + CST_AL) = *(uint2*)lv;
        }
        __syncthreads();                    // P tiles visible

        // ---- mma: A = P (128x32), B = vT (128x32) ----
#pragma unroll
        for (int kk = 0; kk < 2; kk++) {
            uint32_t aH[4][4], aL[4][4], bH[2][4], bL[2][4];
#pragma unroll
            for (int mi = 0; mi < 4; mi++) {
                const int row = wm * 64 + mi * 16 + arow_in;
                const uint32_t ad = stg + swz(row, kk * 2 + akh);
                ldm4(aH[mi], ad + CST_AH);
                ldm4(aL[mi], ad + CST_AL);
            }
#pragma unroll
            for (int nj = 0; nj < 2; nj++) {
                const int row = wn * 32 + nj * 16 + brow_in;
                const uint32_t bd = stg + swz(row, kk * 2 + bkh);
                ldm4(bH[nj], bd + CST_BH);
                ldm4(bL[nj], bd + CST_BL);
            }
#pragma unroll
            for (int mi = 0; mi < 4; mi++)
#pragma unroll
                for (int ni = 0; ni < 4; ni++) {
                    const uint32_t* bh2 = &bH[ni >> 1][(ni & 1) * 2];
                    const uint32_t* bl2 = &bL[ni >> 1][(ni & 1) * 2];
                    mma16816(acc[mi][ni], aH[mi], bh2);
                    mma16816(acc[mi][ni], aH[mi], bl2);
                    mma16816(acc[mi][ni], aL[mi], bh2);
                }
        }
    }
#undef CISSUE
    __syncthreads();
    acc_to_smem(acc);

    const float* ep = (const float*)smem;
    const int r = tid >> 1, half = tid & 1;
    const int b = z / NHEADS, h = z % NHEADS;
    const size_t base = ((size_t)(b * SEQ + m0 + r)) * HIDDEN +
                        h * HDIM + half * 64;
    const float* er = ep + r * EPI_STR + half * 64;
#pragma unroll 8
    for (int cc = 0; cc < 64; cc += 2) {
        __nv_bfloat16 h0, l0, h1, l1;
        split_bf(er[cc], h0, l0); split_bf(er[cc + 1], h1, l1);
        *(__nv_bfloat162*)(g_ch + base + cc) = __nv_bfloat162(h0, h1);
        *(__nv_bfloat162*)(g_cl + base + cc) = __nv_bfloat162(l0, l1);
    }
}

// ===================== 5) out = ctx @ Wd^T + bd + residual ===================
__global__ void __launch_bounds__(256, 2)
out_kernel(const float* __restrict__ bd, const float* __restrict__ residual,
           float* __restrict__ outp) {
    const int m0 = blockIdx.y * 128, n0 = blockIdx.x * 128;

    float acc[4][4][4] = {};
    mma_gemm(g_ch + (size_t)m0 * HIDDEN, g_cl + (size_t)m0 * HIDDEN,
             g_wdh + (size_t)n0 * HIDDEN, g_wdl + (size_t)n0 * HIDDEN,
             HIDDEN, HIDDEN, HIDDEN, acc);
    acc_to_smem(acc);

    extern __shared__ char smem[];
    const float* ep = (const float*)smem;
    const int tid = threadIdx.x;
    const int r = tid >> 1, half = tid & 1;
    const size_t idx = (size_t)(m0 + r) * HIDDEN + n0 + half * 64;
    const float* er = ep + r * EPI_STR + half * 64;
    const float* bi = bd + n0 + half * 64;
    const float* rs = residual + idx;
    float* dst = outp + idx;
#pragma unroll 4
    for (int cc = 0; cc < 64; cc += 4) {
        float4 bv = *(const float4*)(bi + cc);
        float4 rv = *(const float4*)(rs + cc);
        float4 v;
        v.x = er[cc + 0] + bv.x + rv.x;
        v.y = er[cc + 1] + bv.y + rv.y;
        v.z = er[cc + 2] + bv.z + rv.z;
        v.w = er[cc + 3] + bv.w + rv.w;
        *(float4*)(dst + cc) = v;
    }
}

// ===================== launch =================================================
extern "C" void kernel_launch(void* const* d_in, const int* in_sizes, int n_in,
                              void* d_out, int out_size) {
    const float* X        = (const float*)d_in[0];
    const float* residual = (const float*)d_in[1];
    const float* alibi    = (const float*)d_in[2];
    const float* Wq = (const float*)d_in[3];  const float* bq = (const float*)d_in[4];
    const float* Wk = (const float*)d_in[5];  const float* bk = (const float*)d_in[6];
    const float* Wv = (const float*)d_in[7];  const float* bv = (const float*)d_in[8];
    const float* Wd = (const float*)d_in[9];  const float* bd = (const float*)d_in[10];
    float* out = (float*)d_out;

    cudaFuncSetAttribute(qkv_kernel, cudaFuncAttributeMaxDynamicSharedMemorySize, SMEM_DYN);
    cudaFuncSetAttribute(scores_kernel, cudaFuncAttributeMaxDynamicSharedMemorySize, SMEM_DYN);
    cudaFuncSetAttribute(ctx_kernel, cudaFuncAttributeMaxDynamicSharedMemorySize, CSMEM);
    cudaFuncSetAttribute(out_kernel, cudaFuncAttributeMaxDynamicSharedMemorySize, SMEM_DYN);

    dim3 blk(256);
    const int nX4 = MROWS * HIDDEN / 4;
    const int nW4 = HIDDEN * HIDDEN / 4;
    cvt_kernel<<<nX4 / 256, blk>>>(X,  0, nX4);
    cvt_kernel<<<nW4 / 256, blk>>>(Wq, 1, nW4);
    cvt_kernel<<<nW4 / 256, blk>>>(Wk, 2, nW4);
    cvt_kernel<<<nW4 / 256, blk>>>(Wv, 3, nW4);
    cvt_kernel<<<nW4 / 256, blk>>>(Wd, 4, nW4);

    qkv_kernel<<<dim3(16, 32, 3), blk, SMEM_DYN>>>(bq, bk, bv);
    scores_kernel<<<dim3(16, 16, 32), blk, SMEM_DYN>>>(alibi);
    stats_kernel<<<dim3(BH * SEQ), blk>>>();
    ctx_kernel<<<dim3(1, 16, 32), blk, CSMEM>>>();
    out_kernel<<<dim3(16, 32), blk, SMEM_DYN>>>(bd, residual, out);
}